// round 1
// baseline (speedup 1.0000x reference)
#include <cuda_runtime.h>

#define DF 128
#define MAXN 50000
#define MAXE 800000

// Scratch (allocation-free rule: __device__ globals)
__device__ __align__(16) float g_xws[MAXN * DF];   // (x@Wg) * dinv[row]
__device__ __align__(16) float g_agg[MAXN * DF];   // sum over incoming edges (+ self loop)
__device__ float g_dinv[MAXN];
__device__ int   g_deg[MAXN];

// ---------------------------------------------------------------------------
__global__ void k_init_deg(int n) {
    int i = blockIdx.x * blockDim.x + threadIdx.x;
    if (i < n) g_deg[i] = 1;  // self loop
}

__global__ void k_count_deg(const int* __restrict__ ei, int e) {
    int i = blockIdx.x * blockDim.x + threadIdx.x;
    if (i < e) atomicAdd(&g_deg[ei[e + i]], 1);   // dst row of edge_index
}

__global__ void k_dinv(int n) {
    int i = blockIdx.x * blockDim.x + threadIdx.x;
    if (i < n) g_dinv[i] = rsqrtf((float)g_deg[i]);
}

// ---------------------------------------------------------------------------
// xws = (x @ Wg) * dinv[row]; also initializes agg = xws (self-loop term).
// 64 rows/block, 256 threads, Wg (64KB) + x-tile (32KB) in smem.
__global__ __launch_bounds__(256) void k_gemm_xws(const float* __restrict__ x,
                                                  const float* __restrict__ Wg,
                                                  int n) {
    extern __shared__ float sm[];
    float* ws = sm;              // [128][128]
    float* xs = sm + 128 * 128;  // [64][128]
    int tid = threadIdx.x;

    float4* ws4 = (float4*)ws;
    const float4* Wg4 = (const float4*)Wg;
    for (int i = tid; i < 4096; i += 256) ws4[i] = Wg4[i];

    int rbase = blockIdx.x * 64;
    float4* xs4 = (float4*)xs;
    const float4* x4 = (const float4*)x;
    for (int i = tid; i < 2048; i += 256) {
        int r = rbase + (i >> 5);
        xs4[i] = (r < n) ? x4[(size_t)r * 32 + (i & 31)]
                         : make_float4(0.f, 0.f, 0.f, 0.f);
    }
    __syncthreads();

    int rg = tid >> 5;   // 8 row-groups of 8 rows
    int cg = tid & 31;   // 32 col-groups of 4 cols
    float acc[8][4];
#pragma unroll
    for (int ri = 0; ri < 8; ri++)
#pragma unroll
        for (int ci = 0; ci < 4; ci++) acc[ri][ci] = 0.f;

#pragma unroll 4
    for (int k = 0; k < 128; k++) {
        float4 w = ((const float4*)(ws + k * 128))[cg];
#pragma unroll
        for (int ri = 0; ri < 8; ri++) {
            float xv = xs[(rg * 8 + ri) * 128 + k];
            acc[ri][0] = fmaf(xv, w.x, acc[ri][0]);
            acc[ri][1] = fmaf(xv, w.y, acc[ri][1]);
            acc[ri][2] = fmaf(xv, w.z, acc[ri][2]);
            acc[ri][3] = fmaf(xv, w.w, acc[ri][3]);
        }
    }

#pragma unroll
    for (int ri = 0; ri < 8; ri++) {
        int r = rbase + rg * 8 + ri;
        if (r < n) {
            float dv = g_dinv[r];
            float4 o = make_float4(acc[ri][0] * dv, acc[ri][1] * dv,
                                   acc[ri][2] * dv, acc[ri][3] * dv);
            ((float4*)(g_xws + (size_t)r * 128))[cg] = o;
            ((float4*)(g_agg + (size_t)r * 128))[cg] = o;
        }
    }
}

// ---------------------------------------------------------------------------
// One warp per edge: agg[dst] += xws[src], 128 floats = one v4 red per lane.
__global__ __launch_bounds__(256) void k_scatter(const int* __restrict__ ei, int e) {
    int gw = (blockIdx.x * blockDim.x + threadIdx.x) >> 5;
    int lane = threadIdx.x & 31;
    if (gw >= e) return;
    int s = ei[gw];
    int d = ei[e + gw];
    float4 v = ((const float4*)(g_xws + (size_t)s * 128))[lane];
    float* dst = g_agg + (size_t)d * 128 + lane * 4;
    asm volatile("red.global.add.v4.f32 [%0], {%1,%2,%3,%4};"
                 :: "l"(dst), "f"(v.x), "f"(v.y), "f"(v.z), "f"(v.w)
                 : "memory");
}

// ---------------------------------------------------------------------------
// Fused epilogue + 3-layer MLP. 64 nodes/block, 256 threads.
// h   = relu(dinv*agg + bg) + x
// h1  = relu(h @ W1 + b1)          [128 -> 128]
// h2  = relu(h1 @ W2 + b2)         [128 -> 64]
// o   = h2 @ W3 + b3               [64 -> 2]
// out[0:n] = o[:,0], out[n:2n] = o[:,1]
__global__ __launch_bounds__(256) void k_mlp(const float* __restrict__ x,
                                             const float* __restrict__ bg,
                                             const float* __restrict__ W1,
                                             const float* __restrict__ b1,
                                             const float* __restrict__ W2,
                                             const float* __restrict__ b2,
                                             const float* __restrict__ W3,
                                             const float* __restrict__ b3,
                                             float* __restrict__ out, int n) {
    extern __shared__ float sm[];
    float* sW1 = sm;            // 16384
    float* sW2 = sW1 + 16384;   // 8192
    float* sh  = sW2 + 8192;    // 8192 (h, later reused as h2 [64][64])
    float* sh1 = sh + 8192;     // 8192
    float* sW3 = sh1 + 8192;    // 128
    float* sb1 = sW3 + 128;     // 128
    float* sbg = sb1 + 128;     // 128
    float* sb2 = sbg + 128;     // 64
    float* sb3 = sb2 + 64;      // 4 (2 used)
    int tid = threadIdx.x;

    {
        float4* d4 = (float4*)sW1; const float4* s4 = (const float4*)W1;
        for (int i = tid; i < 4096; i += 256) d4[i] = s4[i];
        d4 = (float4*)sW2; s4 = (const float4*)W2;
        for (int i = tid; i < 2048; i += 256) d4[i] = s4[i];
        if (tid < 128) { sW3[tid] = W3[tid]; sb1[tid] = b1[tid]; sbg[tid] = bg[tid]; }
        else if (tid < 192) sb2[tid - 128] = b2[tid - 128];
        else if (tid < 194) sb3[tid - 192] = b3[tid - 192];
    }
    int rbase = blockIdx.x * 64;
    __syncthreads();

    // ---- stage A: h ----
    for (int i = tid; i < 8192; i += 256) {
        int r = i >> 7, dd = i & 127;
        int node = rbase + r;
        float v = 0.f;
        if (node < n) {
            float a = fmaxf(fmaf(g_dinv[node], g_agg[(size_t)node * 128 + dd], sbg[dd]), 0.f);
            v = a + x[(size_t)node * 128 + dd];
        }
        sh[i] = v;
    }
    __syncthreads();

    // ---- stage B: h1 = relu(h @ W1 + b1) ----
    {
        int rg = tid >> 5, cg = tid & 31;
        float acc[8][4];
#pragma unroll
        for (int ri = 0; ri < 8; ri++)
#pragma unroll
            for (int ci = 0; ci < 4; ci++) acc[ri][ci] = 0.f;
#pragma unroll 4
        for (int k = 0; k < 128; k++) {
            float4 w = ((const float4*)(sW1 + k * 128))[cg];
#pragma unroll
            for (int ri = 0; ri < 8; ri++) {
                float xv = sh[(rg * 8 + ri) * 128 + k];
                acc[ri][0] = fmaf(xv, w.x, acc[ri][0]);
                acc[ri][1] = fmaf(xv, w.y, acc[ri][1]);
                acc[ri][2] = fmaf(xv, w.z, acc[ri][2]);
                acc[ri][3] = fmaf(xv, w.w, acc[ri][3]);
            }
        }
#pragma unroll
        for (int ri = 0; ri < 8; ri++) {
            int rr = rg * 8 + ri;
            float4 o;
            o.x = fmaxf(acc[ri][0] + sb1[cg * 4 + 0], 0.f);
            o.y = fmaxf(acc[ri][1] + sb1[cg * 4 + 1], 0.f);
            o.z = fmaxf(acc[ri][2] + sb1[cg * 4 + 2], 0.f);
            o.w = fmaxf(acc[ri][3] + sb1[cg * 4 + 3], 0.f);
            ((float4*)(sh1 + rr * 128))[cg] = o;
        }
    }
    __syncthreads();

    // ---- stage C: h2 = relu(h1 @ W2 + b2), stored into sh as [64][64] ----
    {
        int rg2 = tid >> 4, cg2 = tid & 15;  // 16 row-groups x 4 rows, 16 col-groups x 4 cols
        float acc2[4][4];
#pragma unroll
        for (int ri = 0; ri < 4; ri++)
#pragma unroll
            for (int ci = 0; ci < 4; ci++) acc2[ri][ci] = 0.f;
#pragma unroll 4
        for (int k = 0; k < 128; k++) {
            float4 w = ((const float4*)(sW2 + k * 64))[cg2];
#pragma unroll
            for (int ri = 0; ri < 4; ri++) {
                float xv = sh1[(rg2 * 4 + ri) * 128 + k];
                acc2[ri][0] = fmaf(xv, w.x, acc2[ri][0]);
                acc2[ri][1] = fmaf(xv, w.y, acc2[ri][1]);
                acc2[ri][2] = fmaf(xv, w.z, acc2[ri][2]);
                acc2[ri][3] = fmaf(xv, w.w, acc2[ri][3]);
            }
        }
        __syncthreads();  // sh reads from stage B done before overwrite
#pragma unroll
        for (int ri = 0; ri < 4; ri++) {
            int rr = rg2 * 4 + ri;
#pragma unroll
            for (int ci = 0; ci < 4; ci++)
                sh[rr * 64 + cg2 * 4 + ci] = fmaxf(acc2[ri][ci] + sb2[cg2 * 4 + ci], 0.f);
        }
    }
    __syncthreads();

    // ---- stage D: out = h2 @ W3 + b3 ----
    if (tid < 128) {
        int r = tid >> 1, c = tid & 1;
        float a = sb3[c];
#pragma unroll
        for (int k = 0; k < 64; k++) a = fmaf(sh[r * 64 + k], sW3[k * 2 + c], a);
        int node = rbase + r;
        if (node < n) out[(size_t)c * n + node] = a;
    }
}

// ---------------------------------------------------------------------------
extern "C" void kernel_launch(void* const* d_in, const int* in_sizes, int n_in,
                              void* d_out, int out_size) {
    const float* x  = (const float*)d_in[0];
    const int*   ei = (const int*)d_in[1];
    const float* Wg = (const float*)d_in[2];
    const float* bg = (const float*)d_in[3];
    const float* W1 = (const float*)d_in[4];
    const float* b1 = (const float*)d_in[5];
    const float* W2 = (const float*)d_in[6];
    const float* b2 = (const float*)d_in[7];
    const float* W3 = (const float*)d_in[8];
    const float* b3 = (const float*)d_in[9];
    float* out = (float*)d_out;

    int n = in_sizes[0] / DF;
    int e = in_sizes[1] / 2;

    cudaFuncSetAttribute(k_gemm_xws, cudaFuncAttributeMaxDynamicSharedMemorySize, 98304);
    cudaFuncSetAttribute(k_mlp, cudaFuncAttributeMaxDynamicSharedMemorySize, 165664);

    k_init_deg<<<(n + 255) / 256, 256>>>(n);
    k_count_deg<<<(e + 255) / 256, 256>>>(ei, e);
    k_dinv<<<(n + 255) / 256, 256>>>(n);
    k_gemm_xws<<<(n + 63) / 64, 256, 98304>>>(x, Wg, n);
    k_scatter<<<(e + 7) / 8, 256>>>(ei, e);
    k_mlp<<<(n + 63) / 64, 256, 165664>>>(x, bg, W1, b1, W2, b2, W3, b3, out, n);
}

// round 2
// speedup vs baseline: 1.2364x; 1.2364x over previous
#include <cuda_runtime.h>

#define DF 128
#define MAXN 50000
#define MAXE 800000

// Scratch (allocation-free rule: __device__ globals)
__device__ __align__(16) float g_xws[MAXN * DF];   // (x@Wg) * dinv[row]
__device__ __align__(16) float g_agg[MAXN * DF];   // self-loop + sum over incoming edges
__device__ float g_dinv[MAXN];
__device__ int   g_ecnt[MAXN];      // in-degree (edges only)
__device__ int   g_off[MAXN + 1];   // CSR offsets
__device__ int   g_cur[MAXN];       // fill cursors
__device__ int   g_esrc[MAXE];      // CSR src ids per dst bucket

// ---------------------------------------------------------------------------
__global__ void k_zero_ecnt(int n) {
    int i = blockIdx.x * blockDim.x + threadIdx.x;
    if (i < n) g_ecnt[i] = 0;
}

__global__ void k_count(const int* __restrict__ ei, int e) {
    int i = blockIdx.x * blockDim.x + threadIdx.x;
    if (i < e) atomicAdd(&g_ecnt[ei[e + i]], 1);   // dst row
}

// Single-block scan over n counts -> exclusive offsets, cursors, dinv.
__global__ __launch_bounds__(1024) void k_scan(int n) {
    __shared__ int wsum[32];
    __shared__ int s_carry;
    int tid = threadIdx.x, lane = tid & 31, wid = tid >> 5;
    if (tid == 0) s_carry = 0;
    __syncthreads();
    for (int base = 0; base < n; base += 1024) {
        int i = base + tid;
        int v = (i < n) ? g_ecnt[i] : 0;
        int s = v;
#pragma unroll
        for (int d = 1; d < 32; d <<= 1) {
            int t = __shfl_up_sync(0xffffffffu, s, d);
            if (lane >= d) s += t;
        }
        if (lane == 31) wsum[wid] = s;
        __syncthreads();
        if (wid == 0) {
            int t = wsum[lane];
#pragma unroll
            for (int d = 1; d < 32; d <<= 1) {
                int u = __shfl_up_sync(0xffffffffu, t, d);
                if (lane >= d) t += u;
            }
            wsum[lane] = t;
        }
        __syncthreads();
        int excl = s - v + (wid ? wsum[wid - 1] : 0) + s_carry;
        if (i < n) {
            g_off[i] = excl;
            g_cur[i] = excl;
            g_dinv[i] = rsqrtf((float)(v + 1));  // +1 self loop
        }
        int total = wsum[31];
        __syncthreads();
        if (tid == 0) s_carry += total;
        __syncthreads();
    }
    if (threadIdx.x == 0) g_off[n] = s_carry;
}

__global__ void k_fill(const int* __restrict__ ei, int e) {
    int i = blockIdx.x * blockDim.x + threadIdx.x;
    if (i < e) {
        int s = ei[i];
        int d = ei[e + i];
        int pos = atomicAdd(&g_cur[d], 1);
        g_esrc[pos] = s;
    }
}

// ---------------------------------------------------------------------------
// xws = (x @ Wg) * dinv[row]. 192 rows/block, 768 threads.
__global__ __launch_bounds__(768) void k_gemm_xws(const float* __restrict__ x,
                                                  const float* __restrict__ Wg,
                                                  int n) {
    extern __shared__ float sm[];
    float* ws = sm;              // [128][128]
    float* xs = sm + 16384;      // [192][128]
    int tid = threadIdx.x;

    float4* ws4 = (float4*)ws;
    const float4* Wg4 = (const float4*)Wg;
    for (int i = tid; i < 4096; i += 768) ws4[i] = Wg4[i];

    int rbase = blockIdx.x * 192;
    float4* xs4 = (float4*)xs;
    const float4* x4 = (const float4*)x;
    for (int i = tid; i < 6144; i += 768) {
        int r = rbase + (i >> 5);
        xs4[i] = (r < n) ? x4[(size_t)r * 32 + (i & 31)]
                         : make_float4(0.f, 0.f, 0.f, 0.f);
    }
    __syncthreads();

    int rg = tid >> 5;   // 24 row-groups of 8 rows
    int cg = tid & 31;   // 32 col-groups of 4 cols
    float acc[8][4];
#pragma unroll
    for (int ri = 0; ri < 8; ri++)
#pragma unroll
        for (int ci = 0; ci < 4; ci++) acc[ri][ci] = 0.f;

#pragma unroll 4
    for (int k = 0; k < 128; k++) {
        float4 w = ((const float4*)(ws + k * 128))[cg];
#pragma unroll
        for (int ri = 0; ri < 8; ri++) {
            float xv = xs[(rg * 8 + ri) * 128 + k];
            acc[ri][0] = fmaf(xv, w.x, acc[ri][0]);
            acc[ri][1] = fmaf(xv, w.y, acc[ri][1]);
            acc[ri][2] = fmaf(xv, w.z, acc[ri][2]);
            acc[ri][3] = fmaf(xv, w.w, acc[ri][3]);
        }
    }

#pragma unroll
    for (int ri = 0; ri < 8; ri++) {
        int r = rbase + rg * 8 + ri;
        if (r < n) {
            float dv = g_dinv[r];
            float4 o = make_float4(acc[ri][0] * dv, acc[ri][1] * dv,
                                   acc[ri][2] * dv, acc[ri][3] * dv);
            ((float4*)(g_xws + (size_t)r * 128))[cg] = o;
        }
    }
}

// ---------------------------------------------------------------------------
// One warp per dst node: agg[dst] = xws[dst] + sum_{e in CSR} xws[src].
__global__ __launch_bounds__(256) void k_aggregate(int n) {
    int w = (blockIdx.x * 256 + threadIdx.x) >> 5;
    int lane = threadIdx.x & 31;
    if (w >= n) return;
    const float4* xw4 = (const float4*)g_xws;
    float4 acc = xw4[(size_t)w * 32 + lane];  // self loop
    int beg = g_off[w], end = g_off[w + 1];
    int j = beg;
    for (; j + 4 <= end; j += 4) {
        int s0 = g_esrc[j], s1 = g_esrc[j + 1], s2 = g_esrc[j + 2], s3 = g_esrc[j + 3];
        float4 v0 = xw4[(size_t)s0 * 32 + lane];
        float4 v1 = xw4[(size_t)s1 * 32 + lane];
        float4 v2 = xw4[(size_t)s2 * 32 + lane];
        float4 v3 = xw4[(size_t)s3 * 32 + lane];
        acc.x += v0.x + v1.x + v2.x + v3.x;
        acc.y += v0.y + v1.y + v2.y + v3.y;
        acc.z += v0.z + v1.z + v2.z + v3.z;
        acc.w += v0.w + v1.w + v2.w + v3.w;
    }
    for (; j < end; j++) {
        int s = g_esrc[j];
        float4 v = xw4[(size_t)s * 32 + lane];
        acc.x += v.x; acc.y += v.y; acc.z += v.z; acc.w += v.w;
    }
    ((float4*)g_agg)[(size_t)w * 32 + lane] = acc;
}

// ---------------------------------------------------------------------------
// Fused epilogue + 3-layer MLP. 128 nodes/block, 512 threads.
__global__ __launch_bounds__(512) void k_mlp(const float* __restrict__ x,
                                             const float* __restrict__ bg,
                                             const float* __restrict__ W1,
                                             const float* __restrict__ b1,
                                             const float* __restrict__ W2,
                                             const float* __restrict__ b2,
                                             const float* __restrict__ W3,
                                             const float* __restrict__ b3,
                                             float* __restrict__ out, int n) {
    extern __shared__ float sm[];
    float* sW1 = sm;             // 16384
    float* sW2 = sW1 + 16384;    // 8192
    float* sh  = sW2 + 8192;     // 16384 (h; later reused as h2 [128][64])
    float* sh1 = sh + 16384;     // 16384
    float* sW3 = sh1 + 16384;    // 128
    float* sb1 = sW3 + 128;      // 128
    float* sbg = sb1 + 128;      // 128
    float* sb2 = sbg + 128;      // 64
    float* sb3 = sb2 + 64;       // 2
    int tid = threadIdx.x;

    {
        float4* d4 = (float4*)sW1; const float4* s4 = (const float4*)W1;
        for (int i = tid; i < 4096; i += 512) d4[i] = s4[i];
        d4 = (float4*)sW2; s4 = (const float4*)W2;
        for (int i = tid; i < 2048; i += 512) d4[i] = s4[i];
        if (tid < 128) { sW3[tid] = W3[tid]; sb1[tid] = b1[tid]; sbg[tid] = bg[tid]; }
        else if (tid < 192) sb2[tid - 128] = b2[tid - 128];
        else if (tid < 194) sb3[tid - 192] = b3[tid - 192];
    }
    int rbase = blockIdx.x * 128;
    __syncthreads();

    // ---- stage A: h = relu(dinv*agg + bg) + x ----
    for (int i = tid; i < 16384; i += 512) {
        int r = i >> 7, dd = i & 127;
        int node = rbase + r;
        float v = 0.f;
        if (node < n) {
            float a = fmaxf(fmaf(g_dinv[node], g_agg[(size_t)node * 128 + dd], sbg[dd]), 0.f);
            v = a + x[(size_t)node * 128 + dd];
        }
        sh[i] = v;
    }
    __syncthreads();

    // ---- stage B: h1 = relu(h @ W1 + b1) ----
    {
        int rg = tid >> 5, cg = tid & 31;   // 16 row-groups x 8 rows
        float acc[8][4];
#pragma unroll
        for (int ri = 0; ri < 8; ri++)
#pragma unroll
            for (int ci = 0; ci < 4; ci++) acc[ri][ci] = 0.f;
#pragma unroll 4
        for (int k = 0; k < 128; k++) {
            float4 w = ((const float4*)(sW1 + k * 128))[cg];
#pragma unroll
            for (int ri = 0; ri < 8; ri++) {
                float xv = sh[(rg * 8 + ri) * 128 + k];
                acc[ri][0] = fmaf(xv, w.x, acc[ri][0]);
                acc[ri][1] = fmaf(xv, w.y, acc[ri][1]);
                acc[ri][2] = fmaf(xv, w.z, acc[ri][2]);
                acc[ri][3] = fmaf(xv, w.w, acc[ri][3]);
            }
        }
#pragma unroll
        for (int ri = 0; ri < 8; ri++) {
            int rr = rg * 8 + ri;
            float4 o;
            o.x = fmaxf(acc[ri][0] + sb1[cg * 4 + 0], 0.f);
            o.y = fmaxf(acc[ri][1] + sb1[cg * 4 + 1], 0.f);
            o.z = fmaxf(acc[ri][2] + sb1[cg * 4 + 2], 0.f);
            o.w = fmaxf(acc[ri][3] + sb1[cg * 4 + 3], 0.f);
            ((float4*)(sh1 + rr * 128))[cg] = o;
        }
    }
    __syncthreads();

    // ---- stage C: h2 = relu(h1 @ W2 + b2), stored into sh as [128][64] ----
    {
        int rg2 = tid >> 4, cg2 = tid & 15;  // 32 row-groups x 4 rows, 16 col-groups x 4 cols
        float acc2[4][4];
#pragma unroll
        for (int ri = 0; ri < 4; ri++)
#pragma unroll
            for (int ci = 0; ci < 4; ci++) acc2[ri][ci] = 0.f;
#pragma unroll 4
        for (int k = 0; k < 128; k++) {
            float4 w = ((const float4*)(sW2 + k * 64))[cg2];
#pragma unroll
            for (int ri = 0; ri < 4; ri++) {
                float xv = sh1[(rg2 * 4 + ri) * 128 + k];
                acc2[ri][0] = fmaf(xv, w.x, acc2[ri][0]);
                acc2[ri][1] = fmaf(xv, w.y, acc2[ri][1]);
                acc2[ri][2] = fmaf(xv, w.z, acc2[ri][2]);
                acc2[ri][3] = fmaf(xv, w.w, acc2[ri][3]);
            }
        }
        __syncthreads();  // all stage-B/A readers of sh done before overwrite
#pragma unroll
        for (int ri = 0; ri < 4; ri++) {
            int rr = rg2 * 4 + ri;
#pragma unroll
            for (int ci = 0; ci < 4; ci++)
                sh[rr * 64 + cg2 * 4 + ci] = fmaxf(acc2[ri][ci] + sb2[cg2 * 4 + ci], 0.f);
        }
    }
    __syncthreads();

    // ---- stage D: out = h2 @ W3 + b3 ----
    if (tid < 256) {
        int r = tid >> 1, c = tid & 1;
        float a = sb3[c];
#pragma unroll
        for (int k = 0; k < 64; k++) a = fmaf(sh[r * 64 + k], sW3[k * 2 + c], a);
        int node = rbase + r;
        if (node < n) out[(size_t)c * n + node] = a;
    }
}

// ---------------------------------------------------------------------------
extern "C" void kernel_launch(void* const* d_in, const int* in_sizes, int n_in,
                              void* d_out, int out_size) {
    const float* x  = (const float*)d_in[0];
    const int*   ei = (const int*)d_in[1];
    const float* Wg = (const float*)d_in[2];
    const float* bg = (const float*)d_in[3];
    const float* W1 = (const float*)d_in[4];
    const float* b1 = (const float*)d_in[5];
    const float* W2 = (const float*)d_in[6];
    const float* b2 = (const float*)d_in[7];
    const float* W3 = (const float*)d_in[8];
    const float* b3 = (const float*)d_in[9];
    float* out = (float*)d_out;

    int n = in_sizes[0] / DF;
    int e = in_sizes[1] / 2;

    const int gemm_smem = (16384 + 192 * 128) * 4;                    // 163840
    const int mlp_smem  = (16384 + 8192 + 16384 + 16384 + 450) * 4;   // 231176
    cudaFuncSetAttribute(k_gemm_xws, cudaFuncAttributeMaxDynamicSharedMemorySize, gemm_smem);
    cudaFuncSetAttribute(k_mlp, cudaFuncAttributeMaxDynamicSharedMemorySize, mlp_smem);

    k_zero_ecnt<<<(n + 255) / 256, 256>>>(n);
    k_count<<<(e + 255) / 256, 256>>>(ei, e);
    k_scan<<<1, 1024>>>(n);
    k_gemm_xws<<<(n + 191) / 192, 768, gemm_smem>>>(x, Wg, n);
    k_fill<<<(e + 255) / 256, 256>>>(ei, e);
    k_aggregate<<<(n + 7) / 8, 256>>>(n);
    k_mlp<<<(n + 127) / 128, 512, mlp_smem>>>(x, bg, W1, b1, W2, b2, W3, b3, out, n);
}

// round 3
// speedup vs baseline: 1.2892x; 1.0427x over previous
#include <cuda_runtime.h>

#define DF 128
#define MAXN 50000
#define MAXE 800000

// Scratch (allocation-free rule: __device__ globals)
__device__ __align__(16) float g_xws[MAXN * DF];   // (x@Wg) * dinv[row]
__device__ __align__(16) float g_agg[MAXN * DF];   // self-loop + sum over incoming edges
__device__ float g_dinv[MAXN];
__device__ int   g_ecnt[MAXN];      // in-degree (edges only)
__device__ int   g_off[MAXN + 1];   // CSR offsets
__device__ int   g_cur[MAXN];       // fill cursors
__device__ int   g_esrc[MAXE];      // CSR src ids per dst bucket

// Packed fp32x2 FMA (SASS FFMA2): c += a * b on both lanes, exact fp32.
__device__ __forceinline__ void ffma2(float2& c, const float2 a, const float2 b) {
    asm("fma.rn.f32x2 %0, %1, %2, %0;"
        : "+l"(reinterpret_cast<unsigned long long&>(c))
        : "l"(reinterpret_cast<const unsigned long long&>(a)),
          "l"(reinterpret_cast<const unsigned long long&>(b)));
}

// ---------------------------------------------------------------------------
__global__ void k_zero_ecnt(int n) {
    int i = blockIdx.x * blockDim.x + threadIdx.x;
    if (i < n) g_ecnt[i] = 0;
}

__global__ void k_count(const int* __restrict__ ei, int e) {
    int i = blockIdx.x * blockDim.x + threadIdx.x;
    if (i < e) atomicAdd(&g_ecnt[ei[e + i]], 1);   // dst row
}

// Single-block scan over n counts -> exclusive offsets, cursors, dinv.
__global__ __launch_bounds__(1024) void k_scan(int n) {
    __shared__ int wsum[32];
    __shared__ int s_carry;
    int tid = threadIdx.x, lane = tid & 31, wid = tid >> 5;
    if (tid == 0) s_carry = 0;
    __syncthreads();
    for (int base = 0; base < n; base += 1024) {
        int i = base + tid;
        int v = (i < n) ? g_ecnt[i] : 0;
        int s = v;
#pragma unroll
        for (int d = 1; d < 32; d <<= 1) {
            int t = __shfl_up_sync(0xffffffffu, s, d);
            if (lane >= d) s += t;
        }
        if (lane == 31) wsum[wid] = s;
        __syncthreads();
        if (wid == 0) {
            int t = wsum[lane];
#pragma unroll
            for (int d = 1; d < 32; d <<= 1) {
                int u = __shfl_up_sync(0xffffffffu, t, d);
                if (lane >= d) t += u;
            }
            wsum[lane] = t;
        }
        __syncthreads();
        int excl = s - v + (wid ? wsum[wid - 1] : 0) + s_carry;
        if (i < n) {
            g_off[i] = excl;
            g_cur[i] = excl;
            g_dinv[i] = rsqrtf((float)(v + 1));  // +1 self loop
        }
        int total = wsum[31];
        __syncthreads();
        if (tid == 0) s_carry += total;
        __syncthreads();
    }
    if (threadIdx.x == 0) g_off[n] = s_carry;
}

__global__ void k_fill(const int* __restrict__ ei, int e) {
    int i = blockIdx.x * blockDim.x + threadIdx.x;
    if (i < e) {
        int s = ei[i];
        int d = ei[e + i];
        int pos = atomicAdd(&g_cur[d], 1);
        g_esrc[pos] = s;
    }
}

// ---------------------------------------------------------------------------
// xws = (x @ Wg) * dinv[row]. 192 rows/block, 768 threads, FFMA2 inner loop.
__global__ __launch_bounds__(768) void k_gemm_xws(const float* __restrict__ x,
                                                  const float* __restrict__ Wg,
                                                  int n) {
    extern __shared__ float sm[];
    float* ws = sm;              // [128][128]
    float* xs = sm + 16384;      // [192][128]
    int tid = threadIdx.x;

    float4* ws4 = (float4*)ws;
    const float4* Wg4 = (const float4*)Wg;
    for (int i = tid; i < 4096; i += 768) ws4[i] = Wg4[i];

    int rbase = blockIdx.x * 192;
    float4* xs4 = (float4*)xs;
    const float4* x4 = (const float4*)x;
    for (int i = tid; i < 6144; i += 768) {
        int r = rbase + (i >> 5);
        xs4[i] = (r < n) ? x4[(size_t)r * 32 + (i & 31)]
                         : make_float4(0.f, 0.f, 0.f, 0.f);
    }
    __syncthreads();

    int rg = tid >> 5;   // 24 row-groups of 8 rows
    int cg = tid & 31;   // 32 col-groups of 4 cols
    float2 acc[8][2];
#pragma unroll
    for (int ri = 0; ri < 8; ri++) {
        acc[ri][0] = make_float2(0.f, 0.f);
        acc[ri][1] = make_float2(0.f, 0.f);
    }

    const float* xrow = xs + rg * 8 * 128;
#pragma unroll 4
    for (int k = 0; k < 128; k++) {
        float4 w = ((const float4*)(ws + k * 128))[cg];
        float2 w01 = make_float2(w.x, w.y);
        float2 w23 = make_float2(w.z, w.w);
#pragma unroll
        for (int ri = 0; ri < 8; ri++) {
            float xv = xrow[ri * 128 + k];
            float2 xv2 = make_float2(xv, xv);
            ffma2(acc[ri][0], xv2, w01);
            ffma2(acc[ri][1], xv2, w23);
        }
    }

#pragma unroll
    for (int ri = 0; ri < 8; ri++) {
        int r = rbase + rg * 8 + ri;
        if (r < n) {
            float dv = g_dinv[r];
            float4 o = make_float4(acc[ri][0].x * dv, acc[ri][0].y * dv,
                                   acc[ri][1].x * dv, acc[ri][1].y * dv);
            ((float4*)(g_xws + (size_t)r * 128))[cg] = o;
        }
    }
}

// ---------------------------------------------------------------------------
// One warp per dst node: agg[dst] = xws[dst] + sum_{e in CSR} xws[src].
__global__ __launch_bounds__(256) void k_aggregate(int n) {
    int w = (blockIdx.x * 256 + threadIdx.x) >> 5;
    int lane = threadIdx.x & 31;
    if (w >= n) return;
    const float4* xw4 = (const float4*)g_xws;
    float4 acc = xw4[(size_t)w * 32 + lane];  // self loop
    int beg = g_off[w], end = g_off[w + 1];
    int j = beg;
    for (; j + 4 <= end; j += 4) {
        int s0 = g_esrc[j], s1 = g_esrc[j + 1], s2 = g_esrc[j + 2], s3 = g_esrc[j + 3];
        float4 v0 = xw4[(size_t)s0 * 32 + lane];
        float4 v1 = xw4[(size_t)s1 * 32 + lane];
        float4 v2 = xw4[(size_t)s2 * 32 + lane];
        float4 v3 = xw4[(size_t)s3 * 32 + lane];
        acc.x += v0.x + v1.x + v2.x + v3.x;
        acc.y += v0.y + v1.y + v2.y + v3.y;
        acc.z += v0.z + v1.z + v2.z + v3.z;
        acc.w += v0.w + v1.w + v2.w + v3.w;
    }
    for (; j < end; j++) {
        int s = g_esrc[j];
        float4 v = xw4[(size_t)s * 32 + lane];
        acc.x += v.x; acc.y += v.y; acc.z += v.z; acc.w += v.w;
    }
    ((float4*)g_agg)[(size_t)w * 32 + lane] = acc;
}

// ---------------------------------------------------------------------------
// Fused epilogue + 3-layer MLP. 128 nodes/block, 512 threads, FFMA2 GEMMs.
__global__ __launch_bounds__(512) void k_mlp(const float* __restrict__ x,
                                             const float* __restrict__ bg,
                                             const float* __restrict__ W1,
                                             const float* __restrict__ b1,
                                             const float* __restrict__ W2,
                                             const float* __restrict__ b2,
                                             const float* __restrict__ W3,
                                             const float* __restrict__ b3,
                                             float* __restrict__ out, int n) {
    extern __shared__ float sm[];
    float* sW1 = sm;             // 16384
    float* sW2 = sW1 + 16384;    // 8192
    float* sh  = sW2 + 8192;     // 16384 (h; later reused as h2 [128][64])
    float* sh1 = sh + 16384;     // 16384
    float* sW3 = sh1 + 16384;    // 128
    float* sb1 = sW3 + 128;      // 128
    float* sbg = sb1 + 128;      // 128
    float* sb2 = sbg + 128;      // 64
    float* sb3 = sb2 + 64;       // 2
    int tid = threadIdx.x;

    {
        float4* d4 = (float4*)sW1; const float4* s4 = (const float4*)W1;
        for (int i = tid; i < 4096; i += 512) d4[i] = s4[i];
        d4 = (float4*)sW2; s4 = (const float4*)W2;
        for (int i = tid; i < 2048; i += 512) d4[i] = s4[i];
        if (tid < 128) { sW3[tid] = W3[tid]; sb1[tid] = b1[tid]; sbg[tid] = bg[tid]; }
        else if (tid < 192) sb2[tid - 128] = b2[tid - 128];
        else if (tid < 194) sb3[tid - 192] = b3[tid - 192];
    }
    int rbase = blockIdx.x * 128;
    __syncthreads();

    // ---- stage A: h = relu(dinv*agg + bg) + x ----
    for (int i = tid; i < 16384; i += 512) {
        int r = i >> 7, dd = i & 127;
        int node = rbase + r;
        float v = 0.f;
        if (node < n) {
            float a = fmaxf(fmaf(g_dinv[node], g_agg[(size_t)node * 128 + dd], sbg[dd]), 0.f);
            v = a + x[(size_t)node * 128 + dd];
        }
        sh[i] = v;
    }
    __syncthreads();

    // ---- stage B: h1 = relu(h @ W1 + b1) ----
    {
        int rg = tid >> 5, cg = tid & 31;   // 16 row-groups x 8 rows
        float2 acc[8][2];
#pragma unroll
        for (int ri = 0; ri < 8; ri++) {
            acc[ri][0] = make_float2(0.f, 0.f);
            acc[ri][1] = make_float2(0.f, 0.f);
        }
        const float* hrow = sh + rg * 8 * 128;
#pragma unroll 4
        for (int k = 0; k < 128; k++) {
            float4 w = ((const float4*)(sW1 + k * 128))[cg];
            float2 w01 = make_float2(w.x, w.y);
            float2 w23 = make_float2(w.z, w.w);
#pragma unroll
            for (int ri = 0; ri < 8; ri++) {
                float xv = hrow[ri * 128 + k];
                float2 xv2 = make_float2(xv, xv);
                ffma2(acc[ri][0], xv2, w01);
                ffma2(acc[ri][1], xv2, w23);
            }
        }
#pragma unroll
        for (int ri = 0; ri < 8; ri++) {
            int rr = rg * 8 + ri;
            float4 o;
            o.x = fmaxf(acc[ri][0].x + sb1[cg * 4 + 0], 0.f);
            o.y = fmaxf(acc[ri][0].y + sb1[cg * 4 + 1], 0.f);
            o.z = fmaxf(acc[ri][1].x + sb1[cg * 4 + 2], 0.f);
            o.w = fmaxf(acc[ri][1].y + sb1[cg * 4 + 3], 0.f);
            ((float4*)(sh1 + rr * 128))[cg] = o;
        }
    }
    __syncthreads();

    // ---- stage C: h2 = relu(h1 @ W2 + b2), stored into sh as [128][64] ----
    {
        int rg2 = tid >> 4, cg2 = tid & 15;  // 32 row-groups x 4 rows, 16 col-groups x 4 cols
        float2 acc2[4][2];
#pragma unroll
        for (int ri = 0; ri < 4; ri++) {
            acc2[ri][0] = make_float2(0.f, 0.f);
            acc2[ri][1] = make_float2(0.f, 0.f);
        }
        const float* hrow = sh1 + rg2 * 4 * 128;
#pragma unroll 4
        for (int k = 0; k < 128; k++) {
            float4 w = ((const float4*)(sW2 + k * 64))[cg2];
            float2 w01 = make_float2(w.x, w.y);
            float2 w23 = make_float2(w.z, w.w);
#pragma unroll
            for (int ri = 0; ri < 4; ri++) {
                float xv = hrow[ri * 128 + k];
                float2 xv2 = make_float2(xv, xv);
                ffma2(acc2[ri][0], xv2, w01);
                ffma2(acc2[ri][1], xv2, w23);
            }
        }
        __syncthreads();  // all stage-B/A readers of sh done before overwrite
#pragma unroll
        for (int ri = 0; ri < 4; ri++) {
            int rr = rg2 * 4 + ri;
            sh[rr * 64 + cg2 * 4 + 0] = fmaxf(acc2[ri][0].x + sb2[cg2 * 4 + 0], 0.f);
            sh[rr * 64 + cg2 * 4 + 1] = fmaxf(acc2[ri][0].y + sb2[cg2 * 4 + 1], 0.f);
            sh[rr * 64 + cg2 * 4 + 2] = fmaxf(acc2[ri][1].x + sb2[cg2 * 4 + 2], 0.f);
            sh[rr * 64 + cg2 * 4 + 3] = fmaxf(acc2[ri][1].y + sb2[cg2 * 4 + 3], 0.f);
        }
    }
    __syncthreads();

    // ---- stage D: out = h2 @ W3 + b3 ----
    if (tid < 256) {
        int r = tid >> 1, c = tid & 1;
        float a = sb3[c];
#pragma unroll
        for (int k = 0; k < 64; k++) a = fmaf(sh[r * 64 + k], sW3[k * 2 + c], a);
        int node = rbase + r;
        if (node < n) out[(size_t)c * n + node] = a;
    }
}

// ---------------------------------------------------------------------------
extern "C" void kernel_launch(void* const* d_in, const int* in_sizes, int n_in,
                              void* d_out, int out_size) {
    const float* x  = (const float*)d_in[0];
    const int*   ei = (const int*)d_in[1];
    const float* Wg = (const float*)d_in[2];
    const float* bg = (const float*)d_in[3];
    const float* W1 = (const float*)d_in[4];
    const float* b1 = (const float*)d_in[5];
    const float* W2 = (const float*)d_in[6];
    const float* b2 = (const float*)d_in[7];
    const float* W3 = (const float*)d_in[8];
    const float* b3 = (const float*)d_in[9];
    float* out = (float*)d_out;

    int n = in_sizes[0] / DF;
    int e = in_sizes[1] / 2;

    const int gemm_smem = (16384 + 192 * 128) * 4;                    // 163840
    const int mlp_smem  = (16384 + 8192 + 16384 + 16384 + 450) * 4;   // 231176
    cudaFuncSetAttribute(k_gemm_xws, cudaFuncAttributeMaxDynamicSharedMemorySize, gemm_smem);
    cudaFuncSetAttribute(k_mlp, cudaFuncAttributeMaxDynamicSharedMemorySize, mlp_smem);

    k_zero_ecnt<<<(n + 255) / 256, 256>>>(n);
    k_count<<<(e + 255) / 256, 256>>>(ei, e);
    k_scan<<<1, 1024>>>(n);
    k_gemm_xws<<<(n + 191) / 192, 768, gemm_smem>>>(x, Wg, n);
    k_fill<<<(e + 255) / 256, 256>>>(ei, e);
    k_aggregate<<<(n + 7) / 8, 256>>>(n);
    k_mlp<<<(n + 127) / 128, 512, mlp_smem>>>(x, bg, W1, b1, W2, b2, W3, b3, out, n);
}